// round 2
// baseline (speedup 1.0000x reference)
#include <cuda_runtime.h>
#include <math.h>

#define SEQ  128
#define DIM  128
#define NH   8
#define HDIM 16
#define HIDN 341
#define VOC  8192
#define FEPS 1e-6f
#define XSTRIDE 132   // padded row stride for transposed x in logits smem

// persistent scratch (no cudaMalloc allowed)
__device__ float g_x [SEQ*DIM];
__device__ float g_q [SEQ*DIM];
__device__ float g_k [SEQ*DIM];
__device__ float g_v [SEQ*DIM];
__device__ float g_xn[SEQ*DIM];

__device__ __forceinline__ float sigf(float x) { return 1.f / (1.f + __expf(-x)); }

// ---------------------------------------------------------------------------
// x[s,d] = sigmoid(w_raw[d, idx[s]])
__global__ void embed_kernel(const float* __restrict__ w_raw, const int* __restrict__ idx) {
    int s = blockIdx.x, d = threadIdx.x;
    g_x[s*DIM + d] = sigf(w_raw[d*VOC + idx[s]]);
}

// ---------------------------------------------------------------------------
// per-layer: h = rmsnorm(x)*nw ; q,k,v = h@W ; rope(q,k) ; store q,k,v
// grid = SEQ/2 (2 rows per CTA), block = 384
__global__ void qkv_kernel(const float* __restrict__ nw,
                           const float* __restrict__ wq,
                           const float* __restrict__ wk,
                           const float* __restrict__ wv) {
    __shared__ float h[2][DIM];
    __shared__ float red[2][DIM];
    __shared__ float outs[2][3*DIM];
    int t = threadIdx.x;
    int r0 = blockIdx.x * 2;

    if (t < 256) {
        int r = t >> 7, d = t & 127;
        float xv = g_x[(r0+r)*DIM + d];
        h[r][d] = xv;
        red[r][d] = xv * xv;
    }
    __syncthreads();
    for (int srd = 64; srd >= 1; srd >>= 1) {
        if (t < 256) { int r = t >> 7, d = t & 127; if (d < srd) red[r][d] += red[r][d+srd]; }
        __syncthreads();
    }
    if (t < 256) {
        int r = t >> 7, d = t & 127;
        h[r][d] = h[r][d] * rsqrtf(red[r][0] * (1.f/DIM) + FEPS) * nw[d];
    }
    __syncthreads();

    { // 384 threads: which matrix (q/k/v) x output col; weight loaded once for 2 rows
        int which = t >> 7, n = t & 127;
        const float* W = (which == 0) ? wq : ((which == 1) ? wk : wv);
        float a0 = 0.f, a1 = 0.f;
        #pragma unroll 4
        for (int d = 0; d < DIM; d++) {
            float w = W[d*DIM + n];
            a0 = fmaf(h[0][d], w, a0);
            a1 = fmaf(h[1][d], w, a1);
        }
        outs[0][which*DIM + n] = a0;
        outs[1][which*DIM + n] = a1;
    }
    __syncthreads();

    if (t < 256) { // write v; rope q,k (128 pairs per row)
        int r = t >> 7, p = t & 127;
        int row = r0 + r;
        g_v[row*DIM + p] = outs[r][2*DIM + p];
        int mat = p >> 6, pr = p & 63, hh = pr >> 3, j = pr & 7;
        int base = mat*DIM + hh*HDIM + 2*j;
        float x0 = outs[r][base], x1 = outs[r][base+1];
        float inv = __expf(-1.1512925464970230f * (float)j);  // 10000^(-j/8)
        float f = (float)row * inv;
        float sn, cs; sincosf(f, &sn, &cs);
        float o0 = x0*cs - x1*sn;
        float o1 = x0*sn + x1*cs;
        float* dst = (mat == 0) ? g_q : g_k;
        dst[row*DIM + hh*HDIM + 2*j]     = o0;
        dst[row*DIM + hh*HDIM + 2*j + 1] = o1;
    }
}

// ---------------------------------------------------------------------------
// per-layer: attention + o-proj + residual + rmsnorm + MLP + residual
// grid = SEQ/2 (2 rows per CTA), block = 256, dynamic smem = 128*129*4 (staged K)
__global__ void attn_mlp_kernel(const float* __restrict__ wo,
                                const float* __restrict__ n2w,
                                const float* __restrict__ w1,
                                const float* __restrict__ w3,
                                const float* __restrict__ w2) {
    extern __shared__ float ks[];               // [128][129] padded, conflict-free column reads
    __shared__ float q[2][DIM];
    __shared__ float sc[2][NH][SEQ];
    __shared__ float ctx[2][DIM];
    __shared__ float xr[2][DIM];
    __shared__ float h2[2][DIM];
    __shared__ float red[2][DIM];
    __shared__ float aa[2][HIDN+3];
    int t = threadIdx.x;
    int r0 = blockIdx.x * 2;

    // stage K into smem (coalesced read, padded write)
    for (int i = t; i < SEQ*DIM; i += 256) {
        int j = i >> 7, d = i & 127;
        ks[j*129 + d] = g_k[i];
    }
    for (int i = t; i < 2*DIM; i += 256) {
        int r = i >> 7, d = i & 127;
        q[r][d]  = g_q[(r0+r)*DIM + d];
        xr[r][d] = g_x[(r0+r)*DIM + d];
    }
    __syncthreads();

    int warp = t >> 5, lane = t & 31;
    // scores + softmax: warp = head, both rows sequentially
    for (int r = 0; r < 2; r++) {
        int i = r0 + r;
        float sv[4];
        float m = -1e30f;
        #pragma unroll
        for (int jj = 0; jj < 4; jj++) {
            int j = lane + 32*jj;
            float d0 = -1e30f;
            if (j <= i) {
                const float* kp = ks + j*129 + warp*HDIM;
                const float* qp = q[r] + warp*HDIM;
                float acc = 0.f;
                #pragma unroll
                for (int d = 0; d < HDIM; d++) acc = fmaf(qp[d], kp[d], acc);
                d0 = acc * 0.25f;                         // 1/sqrt(16)
            }
            sv[jj] = d0;
            m = fmaxf(m, d0);
        }
        #pragma unroll
        for (int o = 16; o > 0; o >>= 1) m = fmaxf(m, __shfl_xor_sync(0xffffffffu, m, o));
        float lsum = 0.f;
        #pragma unroll
        for (int jj = 0; jj < 4; jj++) {
            int j = lane + 32*jj;
            float e = (j <= i) ? __expf(sv[jj] - m) : 0.f;
            sv[jj] = e; lsum += e;
        }
        #pragma unroll
        for (int o = 16; o > 0; o >>= 1) lsum += __shfl_xor_sync(0xffffffffu, lsum, o);
        float invs = 1.f / lsum;
        #pragma unroll
        for (int jj = 0; jj < 4; jj++) {
            int j = lane + 32*jj;
            sc[r][warp][j] = sv[jj] * invs;
        }
    }
    __syncthreads();

    // ctx[h*16+d] = sum_j p[h][j] * v[j, h*16+d]   (coalesced v row reads)
    if (t < 128) {
        int hh = t >> 4;
        for (int r = 0; r < 2; r++) {
            int i = r0 + r;
            float acc = 0.f;
            for (int j = 0; j <= i; j++)
                acc = fmaf(sc[r][hh][j], g_v[j*DIM + t], acc);
            ctx[r][t] = acc;
        }
    }
    __syncthreads();

    // o-proj + residual (one weight load serves both rows)
    if (t < 128) {
        int n = t;
        float a0 = 0.f, a1 = 0.f;
        #pragma unroll 4
        for (int d = 0; d < DIM; d++) {
            float w = wo[d*DIM + n];
            a0 = fmaf(ctx[0][d], w, a0);
            a1 = fmaf(ctx[1][d], w, a1);
        }
        float x0 = xr[0][n] + a0, x1 = xr[1][n] + a1;
        xr[0][n] = x0; xr[1][n] = x1;
        red[0][n] = x0*x0; red[1][n] = x1*x1;
    }
    __syncthreads();
    for (int srd = 64; srd >= 1; srd >>= 1) {
        if (t < srd) { red[0][t] += red[0][t+srd]; red[1][t] += red[1][t+srd]; }
        __syncthreads();
    }
    {
        int r = t >> 7, n = t & 127;
        h2[r][n] = xr[r][n] * rsqrtf(red[r][0] * (1.f/DIM) + FEPS) * n2w[n];
    }
    __syncthreads();

    // MLP up: g = h2@w1, u = h2@w3, a = silu(g)*u   (weight load shared across rows)
    for (int k = t; k < HIDN; k += 256) {
        float g0 = 0.f, g1 = 0.f, u0 = 0.f, u1 = 0.f;
        #pragma unroll 4
        for (int d = 0; d < DIM; d++) {
            float wa = w1[d*HIDN + k], wb = w3[d*HIDN + k];
            float ha = h2[0][d],       hb = h2[1][d];
            g0 = fmaf(ha, wa, g0); g1 = fmaf(hb, wa, g1);
            u0 = fmaf(ha, wb, u0); u1 = fmaf(hb, wb, u1);
        }
        aa[0][k] = g0 * sigf(g0) * u0;
        aa[1][k] = g1 * sigf(g1) * u1;
    }
    __syncthreads();

    // MLP down + residual
    if (t < 128) {
        int n = t;
        float a0 = 0.f, a1 = 0.f;
        #pragma unroll 4
        for (int k = 0; k < HIDN; k++) {
            float w = w2[k*DIM + n];
            a0 = fmaf(aa[0][k], w, a0);
            a1 = fmaf(aa[1][k], w, a1);
        }
        g_x[(r0+0)*DIM + n] = xr[0][n] + a0;
        g_x[(r0+1)*DIM + n] = xr[1][n] + a1;
    }
}

// ---------------------------------------------------------------------------
// final rmsnorm + L2 row normalize -> g_xn
__global__ void final_kernel(const float* __restrict__ fw) {
    __shared__ float red[DIM];
    int s = blockIdx.x, d = threadIdx.x;
    float xv = g_x[s*DIM + d];
    red[d] = xv * xv;
    __syncthreads();
    for (int srd = 64; srd >= 1; srd >>= 1) { if (d < srd) red[d] += red[d+srd]; __syncthreads(); }
    float v = xv * rsqrtf(red[0] * (1.f/DIM) + FEPS) * fw[d];
    __syncthreads();
    red[d] = v * v;
    __syncthreads();
    for (int srd = 64; srd >= 1; srd >>= 1) { if (d < srd) red[d] += red[d+srd]; __syncthreads(); }
    g_xn[s*DIM + d] = v * rsqrtf(red[0]);
}

// ---------------------------------------------------------------------------
// logits: grid = VOC/64, block = 256
// smem: xT[128][132] (transposed x_n), bs[128][64] (sigmoid + column-normalized)
__global__ void logits_kernel(const float* __restrict__ w_raw, float* __restrict__ out) {
    extern __shared__ float sm[];
    float* xT = sm;                     // DIM * XSTRIDE
    float* bs = sm + DIM * XSTRIDE;     // DIM * 64
    __shared__ float scale[64];
    int t = threadIdx.x;
    int vbase = blockIdx.x * 64;

    // sigmoid(w_raw) tile, coalesced
    for (int i = t; i < DIM*64; i += 256) {
        int d = i >> 6, vv = i & 63;
        bs[i] = sigf(w_raw[d*VOC + vbase + vv]);
    }
    // transposed x_n (coalesced global read; padded smem write)
    for (int i = t; i < SEQ*DIM; i += 256) {
        int s = i >> 7, d = i & 127;
        xT[d*XSTRIDE + s] = g_xn[i];
    }
    __syncthreads();

    // per-column inverse norm, then normalize in place
    if (t < 64) {
        float ssq = 0.f;
        for (int d = 0; d < DIM; d++) { float b = bs[d*64 + t]; ssq = fmaf(b, b, ssq); }
        scale[t] = rsqrtf(ssq);
    }
    __syncthreads();
    for (int i = t; i < DIM*64; i += 256) bs[i] *= scale[i & 63];
    __syncthreads();

    // main: 4 s-rows x 2 v-cols per thread per tile; warp broadcasts x quad
    int vp = t & 31, sq0 = t >> 5;
    const float invd = 1.f/128.f, lo = 1e-6f, hi = 1.f - 1e-6f;
    for (int sq = sq0; sq < 32; sq += 8) {
        float a00=0,a01=0,a10=0,a11=0,a20=0,a21=0,a30=0,a31=0;
        #pragma unroll 4
        for (int d = 0; d < DIM; d++) {
            float2 b2 = *(const float2*)(bs + d*64 + 2*vp);
            float4 x4 = *(const float4*)(xT + d*XSTRIDE + 4*sq);
            a00 += (x4.x <= b2.x) ? 1.f : b2.x;  a01 += (x4.x <= b2.y) ? 1.f : b2.y;
            a10 += (x4.y <= b2.x) ? 1.f : b2.x;  a11 += (x4.y <= b2.y) ? 1.f : b2.y;
            a20 += (x4.z <= b2.x) ? 1.f : b2.x;  a21 += (x4.z <= b2.y) ? 1.f : b2.y;
            a30 += (x4.w <= b2.x) ? 1.f : b2.x;  a31 += (x4.w <= b2.y) ? 1.f : b2.y;
        }
        int s0 = sq * 4;
        int base = s0*VOC + vbase + 2*vp;
        out[base]             = fminf(fmaxf(a00*invd, lo), hi);
        out[base + 1]         = fminf(fmaxf(a01*invd, lo), hi);
        out[base + VOC]       = fminf(fmaxf(a10*invd, lo), hi);
        out[base + VOC + 1]   = fminf(fmaxf(a11*invd, lo), hi);
        out[base + 2*VOC]     = fminf(fmaxf(a20*invd, lo), hi);
        out[base + 2*VOC + 1] = fminf(fmaxf(a21*invd, lo), hi);
        out[base + 3*VOC]     = fminf(fmaxf(a30*invd, lo), hi);
        out[base + 3*VOC + 1] = fminf(fmaxf(a31*invd, lo), hi);
    }
}

// ---------------------------------------------------------------------------
extern "C" void kernel_launch(void* const* d_in, const int* in_sizes, int n_in,
                              void* d_out, int out_size) {
    const int*   idx   = (const int*)  d_in[0];
    const float* w_raw = (const float*)d_in[1];
    const float* norm1 = (const float*)d_in[2];
    const float* norm2 = (const float*)d_in[3];
    const float* wq    = (const float*)d_in[4];
    const float* wk    = (const float*)d_in[5];
    const float* wv    = (const float*)d_in[6];
    const float* wo    = (const float*)d_in[7];
    const float* w1    = (const float*)d_in[8];
    const float* w3    = (const float*)d_in[9];
    const float* w2    = (const float*)d_in[10];
    const float* fw    = (const float*)d_in[11];
    float* out = (float*)d_out;

    const int ks_bytes     = 128 * 129 * 4;
    const int logits_bytes = (DIM * XSTRIDE + DIM * 64) * 4;
    cudaFuncSetAttribute(attn_mlp_kernel, cudaFuncAttributeMaxDynamicSharedMemorySize, ks_bytes);
    cudaFuncSetAttribute(logits_kernel,   cudaFuncAttributeMaxDynamicSharedMemorySize, logits_bytes);

    embed_kernel<<<SEQ, DIM>>>(w_raw, idx);
    for (int l = 0; l < 2; l++) {
        qkv_kernel<<<SEQ/2, 384>>>(norm1 + l*DIM,
                                   wq + l*DIM*DIM, wk + l*DIM*DIM, wv + l*DIM*DIM);
        attn_mlp_kernel<<<SEQ/2, 256, ks_bytes>>>(wo + l*DIM*DIM, norm2 + l*DIM,
                                                  w1 + l*DIM*HIDN, w3 + l*DIM*HIDN,
                                                  w2 + l*HIDN*DIM);
    }
    final_kernel<<<SEQ, DIM>>>(fw);
    logits_kernel<<<VOC/64, 256, logits_bytes>>>(w_raw, out);
}

// round 3
// speedup vs baseline: 2.0126x; 2.0126x over previous
#include <cuda_runtime.h>
#include <math.h>

#define SEQ  128
#define DIM  128
#define NH   8
#define HIDN 341
#define VOC  8192
#define FEPS 1e-6f
#define NCTA 148
#define TCTA 64      // transformer CTAs, 2 rows each
#define LCTA 128     // logits CTAs, 64 vocab cols each
#define NTHR 256
#define XS   132     // padded (16B-aligned) row stride for transposed x in logits

// ---- persistent scratch (no cudaMalloc allowed) ----
__device__ float g_k2[2][SEQ*DIM];
__device__ float g_v2[2][SEQ*DIM];
__device__ float g_xn[SEQ*DIM];
__device__ unsigned g_cnt = 0;
__device__ unsigned g_gen = 0;

__device__ __forceinline__ float sigf(float x) { return 1.f / (1.f + __expf(-x)); }

// set.le -> 1.0f / 0.0f  (single SASS FSET instead of FSETP+FSEL)
__device__ __forceinline__ float fset_le(float a, float b) {
    float r;
    asm("set.le.f32.f32 %0, %1, %2;" : "=f"(r) : "f"(a), "f"(b));
    return r;
}

// ---- grid-wide barrier (all NCTA CTAs co-resident: grid == #SMs, 1 CTA/SM) ----
__device__ __forceinline__ void gbar() {
    __threadfence();      // publish this thread's global writes
    __syncthreads();
    if (threadIdx.x == 0) {
        unsigned my = *(volatile unsigned*)&g_gen;
        __threadfence();  // order the gen read before the arrival
        unsigned a = atomicAdd(&g_cnt, 1u);
        if (a == NCTA - 1u) {
            g_cnt = 0u;
            __threadfence();
            *(volatile unsigned*)&g_gen = my + 1u;
        } else {
            while (*(volatile unsigned*)&g_gen == my) __nanosleep(64);
        }
        __threadfence();  // acquire
    }
    __syncthreads();
}

// sum over the 128 lanes of row r (=t>>7) of v*v ; safe to call repeatedly (self-syncs)
__device__ __forceinline__ float rowsum_sq(float v, float* red, int t) {
    int lane = t & 31, warp = t >> 5, r = t >> 7;
    float s = v * v;
    #pragma unroll
    for (int o = 16; o > 0; o >>= 1) s += __shfl_xor_sync(0xffffffffu, s, o);
    __syncthreads();                 // protect red from any previous use
    if (lane == 0) red[warp] = s;
    __syncthreads();
    return red[r*4] + red[r*4+1] + red[r*4+2] + red[r*4+3];
}

// smem layout (floats) — transformer view
#define OFF_KS   0                    // 128*129 = 16512 (padded K tile)
#define OFF_VS   16512                // 128*128 = 16384
#define OFF_XR   32896                // 2*128
#define OFF_QR   33152                // 2*128
#define OFF_HH   33408                // 2*128
#define OFF_CTX  33664                // 2*128
#define OFF_SC   33920                // 2*8*128 = 2048
#define OFF_AA   35968                // 2*344 = 688
#define OFF_OUTS 36656                // 2*256 = 512
#define OFF_RED  37168                // 64
#define OFF_PART 37232                // 1024
#define SMEM_FLOATS 38400
// logits view (aliases the same buffer)
#define LOFF_XT  0                    // 128*132 = 16896
#define LOFF_BS  16896                // 8192
#define LOFF_CS  25088                // 8192
#define LOFF_SUM 33280                // 64
#define LOFF_SCL 33344                // 64

extern "C" __global__ void __launch_bounds__(NTHR, 1)
topos_kernel(const int* __restrict__ idx, const float* __restrict__ w_raw,
             const float* __restrict__ norm1, const float* __restrict__ norm2,
             const float* __restrict__ wq, const float* __restrict__ wk,
             const float* __restrict__ wv, const float* __restrict__ wo,
             const float* __restrict__ w1, const float* __restrict__ w3,
             const float* __restrict__ w2, const float* __restrict__ fw,
             float* __restrict__ out)
{
    extern __shared__ float sm[];
    int c = blockIdx.x, t = threadIdx.x;
    bool act = (c < TCTA);
    int r0 = c * 2;

    float* ksv   = sm + OFF_KS;
    float* vsv   = sm + OFF_VS;
    float* xrv   = sm + OFF_XR;
    float* qrv   = sm + OFF_QR;
    float* hhv   = sm + OFF_HH;
    float* ctxv  = sm + OFF_CTX;
    float* scv   = sm + OFF_SC;
    float* aav   = sm + OFF_AA;
    float* outsv = sm + OFF_OUTS;
    float* redv  = sm + OFF_RED;
    float* partv = sm + OFF_PART;

    // ================= embed =================
    if (act) {
        int r = t >> 7, n = t & 127;
        int iv = idx[r0 + r];
        xrv[r*128 + n] = sigf(w_raw[n*VOC + iv]);
    }

    // ================= layers =================
    for (int l = 0; l < 2; l++) {
        const float* wq_l = wq + l*DIM*DIM;
        const float* wk_l = wk + l*DIM*DIM;
        const float* wv_l = wv + l*DIM*DIM;
        const float* wo_l = wo + l*DIM*DIM;
        const float* w1_l = w1 + l*DIM*HIDN;
        const float* w3_l = w3 + l*DIM*HIDN;
        const float* w2_l = w2 + l*HIDN*DIM;
        const float* n1_l = norm1 + l*DIM;
        const float* n2_l = norm2 + l*DIM;

        if (act) {
            int r = t >> 7, n = t & 127;
            // ---- rmsnorm1 ----
            {
                float xv = xrv[r*128 + n];
                float rsum = rowsum_sq(xv, redv, t);
                hhv[r*128 + n] = xv * rsqrtf(rsum * (1.f/128.f) + FEPS) * n1_l[n];
            }
            __syncthreads();

            // ---- qkv: thread t -> col n of (q if t<128 else k); t<128 also col n of v ----
            {
                const float* Wm = (t < 128) ? (wq_l + n) : (wk_l + n);
                const float* Wvp = wv_l + n;
                bool hasv = (t < 128);
                float a0 = 0.f, a1 = 0.f, b0 = 0.f, b1 = 0.f;
                #pragma unroll 1
                for (int d0 = 0; d0 < 128; d0 += 16) {
                    float wa[16], wb[16];
                    #pragma unroll
                    for (int u = 0; u < 16; u++) wa[u] = Wm[(d0+u)*128];
                    if (hasv) {
                        #pragma unroll
                        for (int u = 0; u < 16; u++) wb[u] = Wvp[(d0+u)*128];
                    }
                    #pragma unroll
                    for (int u = 0; u < 16; u++) {
                        float h0 = hhv[d0+u], h1 = hhv[128 + d0+u];
                        a0 = fmaf(h0, wa[u], a0);  a1 = fmaf(h1, wa[u], a1);
                        if (hasv) { b0 = fmaf(h0, wb[u], b0);  b1 = fmaf(h1, wb[u], b1); }
                    }
                }
                outsv[0*256 + t] = a0;   // [row][m*128+n], m=0:q m=1:k
                outsv[1*256 + t] = a1;
                if (hasv) {
                    g_v2[l][(r0+0)*128 + n] = b0;
                    g_v2[l][(r0+1)*128 + n] = b1;
                }
            }
            __syncthreads();

            // ---- rope: one (row, pair) per thread; q -> smem, k -> global ----
            {
                int rr = t >> 7, p = t & 127;
                int row = r0 + rr;
                int mat = p >> 6, pr = p & 63, hd = pr >> 3, j = pr & 7;
                int src = rr*256 + mat*128 + hd*16 + 2*j;
                float x0 = outsv[src], x1 = outsv[src+1];
                float invf = __expf(-1.1512925464970230f * (float)j);  // 10000^(-j/8)
                float f = (float)row * invf;
                float sn, cs0; sincosf(f, &sn, &cs0);
                float o0 = x0*cs0 - x1*sn;
                float o1 = x0*sn + x1*cs0;
                int dd = hd*16 + 2*j;
                if (mat == 0) { qrv[rr*128 + dd] = o0; qrv[rr*128 + dd + 1] = o1; }
                else          { g_k2[l][row*128 + dd] = o0; g_k2[l][row*128 + dd + 1] = o1; }
            }
        }

        gbar();   // all rows' k,v for layer l are published

        if (act) {
            int lane = t & 31, warp = t >> 5;
            // ---- stage K (padded) and V into smem ----
            {
                const float* gk = g_k2[l];
                const float* gv = g_v2[l];
                for (int i = t; i < 128*32; i += NTHR) {
                    int row = i >> 5, q4 = i & 31;
                    float4 kv = ((const float4*)(gk + row*128))[q4];
                    float* dk = ksv + row*129 + q4*4;
                    dk[0] = kv.x; dk[1] = kv.y; dk[2] = kv.z; dk[3] = kv.w;
                    ((float4*)(vsv + row*128))[q4] = ((const float4*)(gv + row*128))[q4];
                }
            }
            __syncthreads();

            // ---- scores + softmax: warp = head, rows sequential ----
            for (int r = 0; r < 2; r++) {
                int i = r0 + r;
                float qreg[16];
                #pragma unroll
                for (int d = 0; d < 16; d++) qreg[d] = qrv[r*128 + warp*16 + d];
                float sv[4];
                float m = -1e30f;
                #pragma unroll
                for (int jj = 0; jj < 4; jj++) {
                    int j = lane + 32*jj;
                    float s = -1e30f;
                    if (j <= i) {
                        const float* kp = ksv + j*129 + warp*16;
                        float acc = 0.f;
                        #pragma unroll
                        for (int d = 0; d < 16; d++) acc = fmaf(qreg[d], kp[d], acc);
                        s = acc * 0.25f;
                    }
                    sv[jj] = s;
                    m = fmaxf(m, s);
                }
                #pragma unroll
                for (int o = 16; o > 0; o >>= 1) m = fmaxf(m, __shfl_xor_sync(0xffffffffu, m, o));
                float lsum = 0.f;
                #pragma unroll
                for (int jj = 0; jj < 4; jj++) {
                    int j = lane + 32*jj;
                    float e = (j <= i) ? __expf(sv[jj] - m) : 0.f;
                    sv[jj] = e; lsum += e;
                }
                #pragma unroll
                for (int o = 16; o > 0; o >>= 1) lsum += __shfl_xor_sync(0xffffffffu, lsum, o);
                float invs = 1.f / lsum;
                #pragma unroll
                for (int jj = 0; jj < 4; jj++)
                    scv[(r*8 + warp)*128 + lane + 32*jj] = sv[jj] * invs;
            }
            __syncthreads();

            // ---- ctx = p @ v ----
            if (t < 128) {
                int hd = t >> 4;
                #pragma unroll
                for (int r = 0; r < 2; r++) {
                    int i = r0 + r;
                    const float* pv = scv + (r*8 + hd)*128;
                    float acc = 0.f;
                    #pragma unroll 4
                    for (int j = 0; j <= i; j++) acc = fmaf(pv[j], vsv[j*128 + t], acc);
                    ctxv[r*128 + t] = acc;
                }
            }
            __syncthreads();

            // ---- o-proj (d split in halves) + residual + rmsnorm2 ----
            {
                int half = t >> 7, n = t & 127;
                const float* Wo = wo_l + half*64*128 + n;
                float a0 = 0.f, a1 = 0.f;
                #pragma unroll 1
                for (int d0 = 0; d0 < 64; d0 += 16) {
                    float wb[16];
                    #pragma unroll
                    for (int u = 0; u < 16; u++) wb[u] = Wo[(d0+u)*128];
                    #pragma unroll
                    for (int u = 0; u < 16; u++) {
                        float c0 = ctxv[half*64 + d0+u], c1 = ctxv[128 + half*64 + d0+u];
                        a0 = fmaf(c0, wb[u], a0);  a1 = fmaf(c1, wb[u], a1);
                    }
                }
                partv[(half*2+0)*128 + n] = a0;
                partv[(half*2+1)*128 + n] = a1;
            }
            __syncthreads();
            {
                int r = t >> 7, n = t & 127;
                float o = partv[r*128 + n] + partv[(2+r)*128 + n];
                float xnew = xrv[r*128 + n] + o;
                xrv[r*128 + n] = xnew;
                float rsum = rowsum_sq(xnew, redv, t);
                hhv[r*128 + n] = xnew * rsqrtf(rsum * (1.f/128.f) + FEPS) * n2_l[n];
            }
            __syncthreads();

            // ---- MLP up, pass 1: cols 0..255 (one per thread) ----
            {
                const float* W1 = w1_l + t;
                const float* W3 = w3_l + t;
                float gg0=0.f, gg1=0.f, uu0=0.f, uu1=0.f;
                #pragma unroll 1
                for (int d0 = 0; d0 < 128; d0 += 8) {
                    float wa[8], wb[8];
                    #pragma unroll
                    for (int u = 0; u < 8; u++) { wa[u] = W1[(d0+u)*HIDN]; wb[u] = W3[(d0+u)*HIDN]; }
                    #pragma unroll
                    for (int u = 0; u < 8; u++) {
                        float h0 = hhv[d0+u], h1 = hhv[128 + d0+u];
                        gg0 = fmaf(h0, wa[u], gg0);  gg1 = fmaf(h1, wa[u], gg1);
                        uu0 = fmaf(h0, wb[u], uu0);  uu1 = fmaf(h1, wb[u], uu1);
                    }
                }
                aav[t]       = gg0 * sigf(gg0) * uu0;
                aav[344 + t] = gg1 * sigf(gg1) * uu1;
            }
            // ---- MLP up, pass 2: cols 256..340, d split in halves ----
            {
                int col = -1, dlo = 0, sl = 0;
                if (t < 85)                    { col = 256 + t;        dlo = 0;  sl = 0; }
                else if (t >= 128 && t < 213)  { col = 256 + (t-128);  dlo = 64; sl = 1; }
                if (col >= 0) {
                    const float* W1 = w1_l + col;
                    const float* W3 = w3_l + col;
                    float gg0=0.f, gg1=0.f, uu0=0.f, uu1=0.f;
                    #pragma unroll 1
                    for (int d0 = dlo; d0 < dlo + 64; d0 += 8) {
                        float wa[8], wb[8];
                        #pragma unroll
                        for (int u = 0; u < 8; u++) { wa[u] = W1[(d0+u)*HIDN]; wb[u] = W3[(d0+u)*HIDN]; }
                        #pragma unroll
                        for (int u = 0; u < 8; u++) {
                            float h0 = hhv[d0+u], h1 = hhv[128 + d0+u];
                            gg0 = fmaf(h0, wa[u], gg0);  gg1 = fmaf(h1, wa[u], gg1);
                            uu0 = fmaf(h0, wb[u], uu0);  uu1 = fmaf(h1, wb[u], uu1);
                        }
                    }
                    int p = col - 256;
                    partv[(sl*4+0)*85 + p] = gg0;
                    partv[(sl*4+1)*85 + p] = gg1;
                    partv[(sl*4+2)*85 + p] = uu0;
                    partv[(sl*4+3)*85 + p] = uu1;
                }
            }
            __syncthreads();
            if (t < 85) {
                float gg0 = partv[0*85+t] + partv[4*85+t];
                float gg1 = partv[1*85+t] + partv[5*85+t];
                float uu0 = partv[2*85+t] + partv[6*85+t];
                float uu1 = partv[3*85+t] + partv[7*85+t];
                aav[256 + t]       = gg0 * sigf(gg0) * uu0;
                aav[344 + 256 + t] = gg1 * sigf(gg1) * uu1;
            }
            __syncthreads();

            // ---- MLP down (k split in halves) + residual ----
            {
                int half = t >> 7, n = t & 127;
                int k0 = half * 171;
                int k1 = half ? HIDN : 171;
                float a0 = 0.f, a1 = 0.f;
                #pragma unroll 1
                for (int kb = k0; kb < k1; kb += 8) {
                    float wb[8];
                    #pragma unroll
                    for (int u = 0; u < 8; u++) {
                        int k = kb + u;
                        wb[u] = (k < k1) ? w2_l[k*128 + n] : 0.f;
                    }
                    #pragma unroll
                    for (int u = 0; u < 8; u++) {
                        int k = kb + u;
                        if (k < k1) {
                            a0 = fmaf(aav[k],       wb[u], a0);
                            a1 = fmaf(aav[344 + k], wb[u], a1);
                        }
                    }
                }
                partv[(half*2+0)*128 + n] = a0;
                partv[(half*2+1)*128 + n] = a1;
            }
            __syncthreads();
            {
                int r = t >> 7, n = t & 127;
                xrv[r*128 + n] += partv[r*128 + n] + partv[(2+r)*128 + n];
            }
            __syncthreads();
        }
    } // layers

    // ================= final norm + L2 normalize -> g_xn =================
    if (act) {
        int r = t >> 7, n = t & 127;
        float xv = xrv[r*128 + n];
        float rsum = rowsum_sq(xv, redv, t);
        float v1 = xv * rsqrtf(rsum * (1.f/128.f) + FEPS) * fw[n];
        float rsum2 = rowsum_sq(v1, redv, t);
        g_xn[(r0 + r)*128 + n] = v1 * rsqrtf(rsum2);
    }

    gbar();   // x_n published

    // ================= logits: CTA c < 128 handles 64 vocab cols =================
    if (c < LCTA) {
        float* xT  = sm + LOFF_XT;
        float* bsv = sm + LOFF_BS;
        float* csv = sm + LOFF_CS;
        float* sumv = sm + LOFF_SUM;
        float* sclv = sm + LOFF_SCL;
        int vbase = c * 64;

        for (int i = t; i < 128*64; i += NTHR) {
            int d = i >> 6, vv = i & 63;
            bsv[i] = sigf(w_raw[d*VOC + vbase + vv]);
        }
        for (int i = t; i < SEQ*DIM; i += NTHR) {
            int s = i >> 7, d = i & 127;
            xT[d*XS + s] = g_xn[i];
        }
        __syncthreads();

        if (t < 64) {
            float ss = 0.f;
            #pragma unroll 4
            for (int d = 0; d < 128; d++) { float b = bsv[d*64 + t]; ss = fmaf(b, b, ss); }
            sclv[t] = rsqrtf(ss);
        }
        __syncthreads();
        for (int i = t; i < 128*64; i += NTHR) {
            float b = bsv[i] * sclv[i & 63];
            bsv[i] = b;
            csv[i] = 1.f - b;
        }
        __syncthreads();
        if (t < 64) {
            float sb = 0.f;
            #pragma unroll 4
            for (int d = 0; d < 128; d++) sb += bsv[d*64 + t];
            sumv[t] = sb;
        }
        __syncthreads();

        // main: 4 s-rows x 2 v-cols per thread per tile
        int vp = t & 31, sq0 = t >> 5;
        const float invd = 1.f/128.f, lo = 1e-6f, hi = 1.f - 1e-6f;
        for (int sq = sq0; sq < 32; sq += 8) {
            float a00=0,a01=0,a10=0,a11=0,a20=0,a21=0,a30=0,a31=0;
            #pragma unroll 4
            for (int d = 0; d < 128; d++) {
                float2 b2 = *(const float2*)(bsv + d*64 + 2*vp);
                float2 c2 = *(const float2*)(csv + d*64 + 2*vp);
                float4 x4 = *(const float4*)(xT + d*XS + 4*sq);
                a00 = fmaf(fset_le(x4.x, b2.x), c2.x, a00);
                a01 = fmaf(fset_le(x4.x, b2.y), c2.y, a01);
                a10 = fmaf(fset_le(x4.y, b2.x), c2.x, a10);
                a11 = fmaf(fset_le(x4.y, b2.y), c2.y, a11);
                a20 = fmaf(fset_le(x4.z, b2.x), c2.x, a20);
                a21 = fmaf(fset_le(x4.z, b2.y), c2.y, a21);
                a30 = fmaf(fset_le(x4.w, b2.x), c2.x, a30);
                a31 = fmaf(fset_le(x4.w, b2.y), c2.y, a31);
            }
            float s0c = sumv[2*vp], s1c = sumv[2*vp + 1];
            int s0 = sq * 4;
            int base = s0*VOC + vbase + 2*vp;
            out[base]             = fminf(fmaxf((s0c + a00)*invd, lo), hi);
            out[base + 1]         = fminf(fmaxf((s1c + a01)*invd, lo), hi);
            out[base + VOC]       = fminf(fmaxf((s0c + a10)*invd, lo), hi);
            out[base + VOC + 1]   = fminf(fmaxf((s1c + a11)*invd, lo), hi);
            out[base + 2*VOC]     = fminf(fmaxf((s0c + a20)*invd, lo), hi);
            out[base + 2*VOC + 1] = fminf(fmaxf((s1c + a21)*invd, lo), hi);
            out[base + 3*VOC]     = fminf(fmaxf((s0c + a30)*invd, lo), hi);
            out[base + 3*VOC + 1] = fminf(fmaxf((s1c + a31)*invd, lo), hi);
        }
    }
}

// ---------------------------------------------------------------------------
extern "C" void kernel_launch(void* const* d_in, const int* in_sizes, int n_in,
                              void* d_out, int out_size) {
    const int*   idx   = (const int*)  d_in[0];
    const float* w_raw = (const float*)d_in[1];
    const float* norm1 = (const float*)d_in[2];
    const float* norm2 = (const float*)d_in[3];
    const float* wq    = (const float*)d_in[4];
    const float* wk    = (const float*)d_in[5];
    const float* wv    = (const float*)d_in[6];
    const float* wo    = (const float*)d_in[7];
    const float* w1    = (const float*)d_in[8];
    const float* w3    = (const float*)d_in[9];
    const float* w2    = (const float*)d_in[10];
    const float* fw    = (const float*)d_in[11];
    float* out = (float*)d_out;

    const int smem_bytes = SMEM_FLOATS * 4;   // 153,600 B
    cudaFuncSetAttribute(topos_kernel, cudaFuncAttributeMaxDynamicSharedMemorySize, smem_bytes);

    topos_kernel<<<NCTA, NTHR, smem_bytes>>>(idx, w_raw, norm1, norm2,
                                             wq, wk, wv, wo, w1, w3, w2, fw, out);
}

// round 4
// speedup vs baseline: 2.7636x; 1.3731x over previous
#include <cuda_runtime.h>
#include <math.h>

#define SEQ  128
#define DIM  128
#define NH   8
#define HIDN 341
#define VOC  8192
#define FEPS 1e-6f
#define NCTA 148
#define TCTA 64      // transformer CTAs (2 rows each)
#define NTHR 512
#define XS   132     // padded row stride for transposed x in logits smem
#define AAS  352     // padded activation stride (341 rounded up, zero tail)
#define PCOLS 98     // logits precompute cols per idle CTA (84*98 >= 8192)

// ---- persistent scratch (no cudaMalloc allowed) ----
__device__ float g_k2[2][SEQ*DIM];
__device__ float g_v2[2][SEQ*DIM];
__device__ float g_xn[SEQ*DIM];
__device__ float g_bs[DIM*VOC];     // normalized sigmoid table b  [d][v]
__device__ float g_cs[DIM*VOC];     // 1-b                         [d][v]
__device__ float g_sum[VOC];        // sum_d b
__device__ unsigned g_cnt_t = 0, g_gen_t = 0;   // transformer barrier (64)
__device__ unsigned g_cnt_a = 0, g_gen_a = 0;   // all-CTA barrier (148)

__device__ __forceinline__ float sigf(float x) { return 1.f / (1.f + __expf(-x)); }

// set.le -> 1.0f / 0.0f
__device__ __forceinline__ float fset_le(float a, float b) {
    float r;
    asm("set.le.f32.f32 %0, %1, %2;" : "=f"(r) : "f"(a), "f"(b));
    return r;
}

// ---- grid-wide barrier among n CTAs (each of those CTAs calls with all threads) ----
__device__ __forceinline__ void gbar_n(unsigned n, unsigned* cnt, volatile unsigned* gen) {
    __threadfence();
    __syncthreads();
    if (threadIdx.x == 0) {
        unsigned my = *gen;
        __threadfence();
        unsigned a = atomicAdd(cnt, 1u);
        if (a == n - 1u) {
            *cnt = 0u;
            __threadfence();
            *gen = my + 1u;
        } else {
            while (*gen == my) __nanosleep(64);
        }
        __threadfence();
    }
    __syncthreads();
}

// sum of v*v over the 128 lanes of row r (= t>>7, valid for t<256); all threads must call
__device__ __forceinline__ float rowsum_sq(float v, float* red, int t) {
    int lane = t & 31, warp = t >> 5, r = t >> 7;
    float s = v * v;
    #pragma unroll
    for (int o = 16; o > 0; o >>= 1) s += __shfl_xor_sync(0xffffffffu, s, o);
    __syncthreads();
    if (lane == 0) red[warp] = s;
    __syncthreads();
    return red[r*4] + red[r*4+1] + red[r*4+2] + red[r*4+3];
}

// smem layout (floats) — transformer view
#define OFF_KS   0        // 128*129 = 16512 (padded K; aliased by MLP partials)
#define OFF_VS   16512    // 128*128
#define OFF_XR   32896    // 2*128
#define OFF_QR   33152    // 2*128
#define OFF_HH   33408    // 2*128
#define OFF_CTX  33664    // 2*128
#define OFF_SC   33920    // 2*8*128 = 2048
#define OFF_AA   35968    // 2*352 = 704
#define OFF_OUTS 36672    // 2*256
#define OFF_RED  37184    // 64
#define OFF_PART 37248    // 1024
#define SMEM_FLOATS 38400
// logits view (aliases)
#define LOFF_XT  0        // 128*132 = 16896
#define LOFF_BS  16896    // 128*64 = 8192
#define LOFF_CS  25088    // 8192
#define LOFF_SUM 33280    // 64

extern "C" __global__ void __launch_bounds__(NTHR, 1)
topos_kernel(const int* __restrict__ idx, const float* __restrict__ w_raw,
             const float* __restrict__ norm1, const float* __restrict__ norm2,
             const float* __restrict__ wq, const float* __restrict__ wk,
             const float* __restrict__ wv, const float* __restrict__ wo,
             const float* __restrict__ w1, const float* __restrict__ w3,
             const float* __restrict__ w2, const float* __restrict__ fw,
             float* __restrict__ out)
{
    extern __shared__ float sm[];
    int c = blockIdx.x, t = threadIdx.x;
    bool act = (c < TCTA);
    int r0 = c * 2;

    float* ksv   = sm + OFF_KS;
    float* vsv   = sm + OFF_VS;
    float* xrv   = sm + OFF_XR;
    float* qrv   = sm + OFF_QR;
    float* hhv   = sm + OFF_HH;
    float* ctxv  = sm + OFF_CTX;
    float* scv   = sm + OFF_SC;
    float* aav   = sm + OFF_AA;
    float* outsv = sm + OFF_OUTS;
    float* redv  = sm + OFF_RED;
    float* partv = sm + OFF_PART;
    float* mpart = sm + OFF_KS;     // alias: MLP-up partials (1023*4 = 4092 floats)

    if (act) {
        // ========================= transformer: CTA owns rows r0, r0+1 =========================
        // embed + zero aav tail
        if (t < 256) {
            int r = t >> 7, n = t & 127;
            xrv[r*128 + n] = sigf(w_raw[n*VOC + idx[r0 + r]]);
        }
        if (t < 11) { aav[341 + t] = 0.f; aav[AAS + 341 + t] = 0.f; }
        __syncthreads();

        for (int l = 0; l < 2; l++) {
            const float* wq_l = wq + l*DIM*DIM;
            const float* wk_l = wk + l*DIM*DIM;
            const float* wv_l = wv + l*DIM*DIM;
            const float* wo_l = wo + l*DIM*DIM;
            const float* w1_l = w1 + l*DIM*HIDN;
            const float* w3_l = w3 + l*DIM*HIDN;
            const float* w2_l = w2 + l*HIDN*DIM;

            // ---- rmsnorm1 ----
            {
                int r = t >> 7, n = t & 127;
                float xv = (t < 256) ? xrv[r*128 + n] : 0.f;
                float rsum = rowsum_sq(xv, redv, t);
                if (t < 256)
                    hhv[r*128 + n] = xv * rsqrtf(rsum * (1.f/128.f) + FEPS) * norm1[l*DIM + n];
            }
            __syncthreads();

            // ---- qkv: t<384 -> one full-d output column (q/k/v) for both rows ----
            if (t < 384) {
                int n = t & 127;
                const float* W = ((t < 128) ? wq_l : (t < 256) ? wk_l : wv_l) + n;
                float a0 = 0.f, a1 = 0.f;
                #pragma unroll 1
                for (int d0 = 0; d0 < 128; d0 += 32) {
                    float w[32];
                    #pragma unroll
                    for (int u = 0; u < 32; u++) w[u] = W[(d0+u)*128];
                    #pragma unroll
                    for (int u = 0; u < 32; u++) {
                        a0 = fmaf(hhv[d0+u],       w[u], a0);
                        a1 = fmaf(hhv[128 + d0+u], w[u], a1);
                    }
                }
                if (t < 256) {                   // q (mat 0) / k (mat 1)
                    outsv[0*256 + t] = a0;
                    outsv[1*256 + t] = a1;
                } else {                         // v straight to global
                    g_v2[l][(r0+0)*128 + n] = a0;
                    g_v2[l][(r0+1)*128 + n] = a1;
                }
            }
            __syncthreads();

            // ---- rope: (row, pair) per thread; q -> smem, k -> global ----
            if (t < 256) {
                int rr = t >> 7, p = t & 127;
                int row = r0 + rr;
                int mat = p >> 6, pr = p & 63, hd = pr >> 3, j = pr & 7;
                int src = rr*256 + mat*128 + hd*16 + 2*j;
                float x0 = outsv[src], x1 = outsv[src+1];
                float invf = __expf(-1.1512925464970230f * (float)j);  // 10000^(-j/8)
                float f = (float)row * invf;
                float sn, cs0; sincosf(f, &sn, &cs0);
                float o0 = x0*cs0 - x1*sn;
                float o1 = x0*sn + x1*cs0;
                int dd = hd*16 + 2*j;
                if (mat == 0) { qrv[rr*128 + dd] = o0; qrv[rr*128 + dd + 1] = o1; }
                else          { g_k2[l][row*128 + dd] = o0; g_k2[l][row*128 + dd + 1] = o1; }
            }

            gbar_n(TCTA, &g_cnt_t, &g_gen_t);   // k,v of layer l published (64 CTAs)

            // ---- stage K (padded) + V ----
            {
                const float* gk = g_k2[l];
                const float* gv = g_v2[l];
                for (int i = t; i < 128*32; i += NTHR) {
                    int row = i >> 5, q4 = i & 31;
                    float4 kv = ((const float4*)(gk + row*128))[q4];
                    float* dk = ksv + row*129 + q4*4;
                    dk[0] = kv.x; dk[1] = kv.y; dk[2] = kv.z; dk[3] = kv.w;
                    ((float4*)(vsv + row*128))[q4] = ((const float4*)(gv + row*128))[q4];
                }
            }
            __syncthreads();

            // ---- scores + softmax: 16 warps = 2 rows x 8 heads ----
            {
                int lane = t & 31, warp = t >> 5;
                int r = warp >> 3, head = warp & 7;
                int i = r0 + r;
                float qreg[16];
                #pragma unroll
                for (int d = 0; d < 16; d++) qreg[d] = qrv[r*128 + head*16 + d];
                float sv[4];
                float m = -1e30f;
                #pragma unroll
                for (int jj = 0; jj < 4; jj++) {
                    int j = lane + 32*jj;
                    float s = -1e30f;
                    if (j <= i) {
                        const float* kp = ksv + j*129 + head*16;
                        float acc = 0.f;
                        #pragma unroll
                        for (int d = 0; d < 16; d++) acc = fmaf(qreg[d], kp[d], acc);
                        s = acc * 0.25f;
                    }
                    sv[jj] = s;
                    m = fmaxf(m, s);
                }
                #pragma unroll
                for (int o = 16; o > 0; o >>= 1) m = fmaxf(m, __shfl_xor_sync(0xffffffffu, m, o));
                float lsum = 0.f;
                #pragma unroll
                for (int jj = 0; jj < 4; jj++) {
                    int j = lane + 32*jj;
                    float e = (j <= i) ? __expf(sv[jj] - m) : 0.f;
                    sv[jj] = e; lsum += e;
                }
                #pragma unroll
                for (int o = 16; o > 0; o >>= 1) lsum += __shfl_xor_sync(0xffffffffu, lsum, o);
                float invs = 1.f / lsum;
                #pragma unroll
                for (int jj = 0; jj < 4; jj++)
                    scv[(r*8 + head)*128 + lane + 32*jj] = sv[jj] * invs;   // zeros beyond i
            }
            __syncthreads();

            // ---- ctx = p @ v (both rows in parallel; probs are zero past causal bound) ----
            if (t < 256) {
                int r = t >> 7, n = t & 127, hd = (n >> 4);
                const float* pv = scv + (r*8 + hd)*128;
                float ac0=0.f, ac1=0.f, ac2=0.f, ac3=0.f;
                #pragma unroll 8
                for (int j = 0; j < 128; j += 4) {
                    ac0 = fmaf(pv[j],   vsv[j*128 + n],       ac0);
                    ac1 = fmaf(pv[j+1], vsv[(j+1)*128 + n],   ac1);
                    ac2 = fmaf(pv[j+2], vsv[(j+2)*128 + n],   ac2);
                    ac3 = fmaf(pv[j+3], vsv[(j+3)*128 + n],   ac3);
                }
                ctxv[r*128 + n] = (ac0 + ac1) + (ac2 + ac3);
            }
            __syncthreads();

            // ---- o-proj: 128 cols x 4 d-quarters ----
            {
                int n = t & 127, quar = t >> 7;
                const float* Wo = wo_l + (quar*32)*128 + n;
                float w[32];
                #pragma unroll
                for (int u = 0; u < 32; u++) w[u] = Wo[u*128];
                float a0 = 0.f, a1 = 0.f;
                #pragma unroll
                for (int u = 0; u < 32; u++) {
                    a0 = fmaf(ctxv[quar*32 + u],       w[u], a0);
                    a1 = fmaf(ctxv[128 + quar*32 + u], w[u], a1);
                }
                partv[quar*256 + 0*128 + n] = a0;
                partv[quar*256 + 1*128 + n] = a1;
            }
            __syncthreads();

            // ---- residual + rmsnorm2 ----
            {
                int r = t >> 7, n = t & 127;
                float xnew = 0.f;
                if (t < 256) {
                    float o = partv[0*256 + r*128 + n] + partv[1*256 + r*128 + n]
                            + partv[2*256 + r*128 + n] + partv[3*256 + r*128 + n];
                    xnew = xrv[r*128 + n] + o;
                    xrv[r*128 + n] = xnew;
                }
                float rsum = rowsum_sq(xnew, redv, t);
                if (t < 256)
                    hhv[r*128 + n] = xnew * rsqrtf(rsum * (1.f/128.f) + FEPS) * norm2[l*DIM + n];
            }
            __syncthreads();

            // ---- MLP up: 1023 tasks = 341 cols x 3 d-segments (48/48/32) ----
            for (int task = t; task < 1023; task += NTHR) {
                int col = task / 3, seg = task - col*3;
                int d0 = seg * 48;
                int d1 = (seg == 2) ? 128 : d0 + 48;
                const float* W1 = w1_l + col;
                const float* W3 = w3_l + col;
                float gg0=0.f, gg1=0.f, uu0=0.f, uu1=0.f;
                #pragma unroll 1
                for (int db = d0; db < d1; db += 16) {
                    float wa[16], wb[16];
                    #pragma unroll
                    for (int u = 0; u < 16; u++) { wa[u] = W1[(db+u)*HIDN]; wb[u] = W3[(db+u)*HIDN]; }
                    #pragma unroll
                    for (int u = 0; u < 16; u++) {
                        float h0 = hhv[db+u], h1 = hhv[128 + db+u];
                        gg0 = fmaf(h0, wa[u], gg0);  gg1 = fmaf(h1, wa[u], gg1);
                        uu0 = fmaf(h0, wb[u], uu0);  uu1 = fmaf(h1, wb[u], uu1);
                    }
                }
                mpart[task*4+0] = gg0;  mpart[task*4+1] = gg1;
                mpart[task*4+2] = uu0;  mpart[task*4+3] = uu1;
            }
            __syncthreads();
            // reduce + silu
            if (t < 341) {
                int b0 = (t*3)*4;
                float gg0 = mpart[b0+0] + mpart[b0+4] + mpart[b0+8];
                float gg1 = mpart[b0+1] + mpart[b0+5] + mpart[b0+9];
                float uu0 = mpart[b0+2] + mpart[b0+6] + mpart[b0+10];
                float uu1 = mpart[b0+3] + mpart[b0+7] + mpart[b0+11];
                aav[t]       = gg0 * sigf(gg0) * uu0;
                aav[AAS + t] = gg1 * sigf(gg1) * uu1;
            }
            __syncthreads();

            // ---- MLP down: 128 cols x 4 k-quarters (86/85/85/85) ----
            {
                int n = t & 127, kq = t >> 7;
                int k0 = (kq == 0) ? 0 : 86 + (kq-1)*85;
                int k1 = (kq == 0) ? 86 : k0 + 85;
                float a0 = 0.f, a1 = 0.f;
                #pragma unroll 1
                for (int kb = k0; kb < k1; kb += 16) {
                    float w[16];
                    #pragma unroll
                    for (int u = 0; u < 16; u++)
                        w[u] = (kb+u < k1) ? w2_l[(kb+u)*128 + n] : 0.f;
                    #pragma unroll
                    for (int u = 0; u < 16; u++) {
                        a0 = fmaf(aav[kb+u],       w[u], a0);   // aav zero-padded past 340
                        a1 = fmaf(aav[AAS + kb+u], w[u], a1);
                    }
                }
                partv[kq*256 + 0*128 + n] = a0;
                partv[kq*256 + 1*128 + n] = a1;
            }
            __syncthreads();
            if (t < 256) {
                int r = t >> 7, n = t & 127;
                xrv[r*128 + n] += partv[0*256 + r*128 + n] + partv[1*256 + r*128 + n]
                                + partv[2*256 + r*128 + n] + partv[3*256 + r*128 + n];
            }
            __syncthreads();
        } // layers

        // ---- final rmsnorm + L2 normalize -> g_xn ----
        {
            int r = t >> 7, n = t & 127;
            float xv = (t < 256) ? xrv[r*128 + n] : 0.f;
            float rsum = rowsum_sq(xv, redv, t);
            float v1 = xv * rsqrtf(rsum * (1.f/128.f) + FEPS) * ((t < 256) ? fw[n] : 0.f);
            float rsum2 = rowsum_sq(v1, redv, t);
            if (t < 256)
                g_xn[(r0 + r)*128 + n] = v1 * rsqrtf(rsum2);
        }
    } else {
        // ========================= idle CTAs: logits table precompute =========================
        int i = c - TCTA;                        // 0..83
        if (t < PCOLS) {
            int cj = i*PCOLS + t;
            if (cj < VOC) {
                const float* W = w_raw + cj;
                // pass 1: sum of squares of sigmoid
                float ssq = 0.f;
                #pragma unroll 1
                for (int d0 = 0; d0 < 128; d0 += 16) {
                    float w[16];
                    #pragma unroll
                    for (int u = 0; u < 16; u++) w[u] = W[(d0+u)*VOC];
                    #pragma unroll
                    for (int u = 0; u < 16; u++) { float b = sigf(w[u]); ssq = fmaf(b, b, ssq); }
                }
                float scale = rsqrtf(ssq);
                // pass 2: write b, 1-b, accumulate column sum
                float csum = 0.f;
                #pragma unroll 1
                for (int d0 = 0; d0 < 128; d0 += 16) {
                    float w[16];
                    #pragma unroll
                    for (int u = 0; u < 16; u++) w[u] = W[(d0+u)*VOC];
                    #pragma unroll
                    for (int u = 0; u < 16; u++) {
                        float b = sigf(w[u]) * scale;
                        csum += b;
                        g_bs[(d0+u)*VOC + cj] = b;
                        g_cs[(d0+u)*VOC + cj] = 1.f - b;
                    }
                }
                g_sum[cj] = csum;
            }
        }
    }

    gbar_n(NCTA, &g_cnt_a, &g_gen_a);   // x_n + logits tables published (all 148)

    // ========================= logits main: CTA c<128 handles 64 vocab cols =========================
    if (c < 128) {
        float* xT   = sm + LOFF_XT;
        float* bst  = sm + LOFF_BS;
        float* cst  = sm + LOFF_CS;
        float* sumv = sm + LOFF_SUM;
        int col0 = c * 64;

        for (int i = t; i < 128*16; i += NTHR) {
            int d = i >> 4, j4 = i & 15;
            ((float4*)(bst + d*64))[j4] = ((const float4*)(g_bs + d*VOC + col0))[j4];
            ((float4*)(cst + d*64))[j4] = ((const float4*)(g_cs + d*VOC + col0))[j4];
        }
        for (int i = t; i < SEQ*DIM; i += NTHR) {
            int s = i >> 7, d = i & 127;
            xT[d*XS + s] = g_xn[i];
        }
        if (t < 64) sumv[t] = g_sum[col0 + t];
        __syncthreads();

        // thread tile: 8 rows x 2 cols; vp = t&31 (cols), sq = t>>5 (row group of 8)
        int vp = t & 31, sq = t >> 5;
        const float invd = 1.f/128.f, lo = 1e-6f, hi = 1.f - 1e-6f;
        float acA[8] = {0,0,0,0,0,0,0,0};
        float acB[8] = {0,0,0,0,0,0,0,0};
        #pragma unroll 4
        for (int d = 0; d < 128; d++) {
            const float* xr = xT + d*XS + 8*sq;
            float4 xa = *(const float4*)(xr);
            float4 xb = *(const float4*)(xr + 4);
            float2 b2 = *(const float2*)(bst + d*64 + 2*vp);
            float2 c2 = *(const float2*)(cst + d*64 + 2*vp);
            acA[0] = fmaf(fset_le(xa.x, b2.x), c2.x, acA[0]);
            acB[0] = fmaf(fset_le(xa.x, b2.y), c2.y, acB[0]);
            acA[1] = fmaf(fset_le(xa.y, b2.x), c2.x, acA[1]);
            acB[1] = fmaf(fset_le(xa.y, b2.y), c2.y, acB[1]);
            acA[2] = fmaf(fset_le(xa.z, b2.x), c2.x, acA[2]);
            acB[2] = fmaf(fset_le(xa.z, b2.y), c2.y, acB[2]);
            acA[3] = fmaf(fset_le(xa.w, b2.x), c2.x, acA[3]);
            acB[3] = fmaf(fset_le(xa.w, b2.y), c2.y, acB[3]);
            acA[4] = fmaf(fset_le(xb.x, b2.x), c2.x, acA[4]);
            acB[4] = fmaf(fset_le(xb.x, b2.y), c2.y, acB[4]);
            acA[5] = fmaf(fset_le(xb.y, b2.x), c2.x, acA[5]);
            acB[5] = fmaf(fset_le(xb.y, b2.y), c2.y, acB[5]);
            acA[6] = fmaf(fset_le(xb.z, b2.x), c2.x, acA[6]);
            acB[6] = fmaf(fset_le(xb.z, b2.y), c2.y, acB[6]);
            acA[7] = fmaf(fset_le(xb.w, b2.x), c2.x, acA[7]);
            acB[7] = fmaf(fset_le(xb.w, b2.y), c2.y, acB[7]);
        }
        float sA = sumv[2*vp], sB = sumv[2*vp + 1];
        #pragma unroll
        for (int rr = 0; rr < 8; rr++) {
            float2 o;
            o.x = fminf(fmaxf((sA + acA[rr]) * invd, lo), hi);
            o.y = fminf(fmaxf((sB + acB[rr]) * invd, lo), hi);
            *(float2*)(out + (8*sq + rr)*VOC + col0 + 2*vp) = o;
        }
    }
}

// ---------------------------------------------------------------------------
extern "C" void kernel_launch(void* const* d_in, const int* in_sizes, int n_in,
                              void* d_out, int out_size) {
    const int*   idx   = (const int*)  d_in[0];
    const float* w_raw = (const float*)d_in[1];
    const float* norm1 = (const float*)d_in[2];
    const float* norm2 = (const float*)d_in[3];
    const float* wq    = (const float*)d_in[4];
    const float* wk    = (const float*)d_in[5];
    const float* wv    = (const float*)d_in[6];
    const float* wo    = (const float*)d_in[7];
    const float* w1    = (const float*)d_in[8];
    const float* w3    = (const float*)d_in[9];
    const float* w2    = (const float*)d_in[10];
    const float* fw    = (const float*)d_in[11];
    float* out = (float*)d_out;

    const int smem_bytes = SMEM_FLOATS * 4;   // 153,600 B
    cudaFuncSetAttribute(topos_kernel, cudaFuncAttributeMaxDynamicSharedMemorySize, smem_bytes);

    topos_kernel<<<NCTA, NTHR, smem_bytes>>>(idx, w_raw, norm1, norm2,
                                             wq, wk, wv, wo, w1, w3, w2, fw, out);
}